// round 10
// baseline (speedup 1.0000x reference)
#include <cuda_runtime.h>

typedef unsigned long long ull;

#define T_STEPS 1024
#define BATCH   64
#define NCTA    128
#define NTHR    768

// Per-step input vector v (K=1024 rows x 64 batch) read DIRECTLY from global (L2):
//   rows [0,256)    = x_t        (layer0 only)
//   rows [256,768)  = h0_{t-1}   (both layers)
//   rows [768,1024) = h1_{t-2}   (layer1 only)
// Contiguous k-split: warp ks (0..23) owns k in [32ks,32ks+32) for L0 and the same
// local k1 range for L1 -> each v row read by exactly one warp, no staging.
// L0 and L1 GEMMs INTERLEAVED row-by-row in one loop: 2 independent LDG streams,
// 24 ffma2 between a load and its use -> L2 latency covered at prefetch distance 1.
// Lane: pg = (lane>>1) in [0,16) -> pairs 2pg,2pg+1; cl = lane&1 -> col half.
// Accums: a0[16] + a1[8] = 24 ull. 24 ks-partials reduced in TWO waves (12 slots).

__device__ float g_xT[T_STEPS * 256 * BATCH];   // x transposed to [t][k][b]
__device__ float g_h0[2][512 * BATCH];
__device__ float g_h1[2][256 * BATCH];
__device__ unsigned g_count = 0;
__device__ volatile unsigned g_phase = 0;

__device__ __forceinline__ ull ffma2(ull a, ull b, ull c) {
    ull d;
    asm("fma.rn.f32x2 %0, %1, %2, %3;" : "=l"(d) : "l"(a), "l"(b), "l"(c));
    return d;
}
__device__ __forceinline__ ull addf2(ull a, ull b) {
    ull d;
    asm("add.rn.f32x2 %0, %1, %2;" : "=l"(d) : "l"(a), "l"(b));
    return d;
}
__device__ __forceinline__ ull dup32(float w) {
    unsigned u = __float_as_uint(w);
    return ((ull)u << 32) | (ull)u;
}
__device__ __forceinline__ float sigmf(float x) {
    return 1.0f / (1.0f + __expf(-x));
}

// Sense-reversing grid barrier. Safe: ~222KB smem -> 1 CTA/SM, 128 CTAs <= 148 SMs,
// all co-resident in wave 1. Count self-resets -> consistent across graph replays.
__device__ __forceinline__ void grid_barrier() {
    __syncthreads();
    if (threadIdx.x == 0) {
        __threadfence();
        unsigned ph = g_phase;
        if (atomicAdd(&g_count, 1u) == (unsigned)(gridDim.x - 1)) {
            atomicExch(&g_count, 0u);
            __threadfence();
            g_phase = ph + 1u;
        } else {
            while (g_phase == ph) { __nanosleep(32); }
            __threadfence();
        }
    }
    __syncthreads();
}

// One k-row of both layers: 16 + 8 ffma2, weights via broadcast LDS.128.
__device__ __forceinline__ void fma_row(const ull* __restrict__ wp0,
                                        const ull* __restrict__ wp1,
                                        ulonglong2 v0, ulonglong2 v1,
                                        ull* __restrict__ a0, ull* __restrict__ a1) {
    ulonglong2 wA = *reinterpret_cast<const ulonglong2*>(wp0);
    ulonglong2 wB = *reinterpret_cast<const ulonglong2*>(wp0 + 2);
    a0[0]  = ffma2(wA.x, v0.x, a0[0]);   a0[1]  = ffma2(wA.x, v0.y, a0[1]);
    a0[2]  = ffma2(wA.y, v0.x, a0[2]);   a0[3]  = ffma2(wA.y, v0.y, a0[3]);
    a0[4]  = ffma2(wB.x, v0.x, a0[4]);   a0[5]  = ffma2(wB.x, v0.y, a0[5]);
    a0[6]  = ffma2(wB.y, v0.x, a0[6]);   a0[7]  = ffma2(wB.y, v0.y, a0[7]);
    ulonglong2 wC = *reinterpret_cast<const ulonglong2*>(wp0 + 4);
    ulonglong2 wD = *reinterpret_cast<const ulonglong2*>(wp0 + 6);
    a0[8]  = ffma2(wC.x, v0.x, a0[8]);   a0[9]  = ffma2(wC.x, v0.y, a0[9]);
    a0[10] = ffma2(wC.y, v0.x, a0[10]);  a0[11] = ffma2(wC.y, v0.y, a0[11]);
    a0[12] = ffma2(wD.x, v0.x, a0[12]);  a0[13] = ffma2(wD.x, v0.y, a0[13]);
    a0[14] = ffma2(wD.y, v0.x, a0[14]);  a0[15] = ffma2(wD.y, v0.y, a0[15]);
    ulonglong2 wE = *reinterpret_cast<const ulonglong2*>(wp1);
    ulonglong2 wF = *reinterpret_cast<const ulonglong2*>(wp1 + 2);
    a1[0]  = ffma2(wE.x, v1.x, a1[0]);   a1[1]  = ffma2(wE.x, v1.y, a1[1]);
    a1[2]  = ffma2(wE.y, v1.x, a1[2]);   a1[3]  = ffma2(wE.y, v1.y, a1[3]);
    a1[4]  = ffma2(wF.x, v1.x, a1[4]);   a1[5]  = ffma2(wF.x, v1.y, a1[5]);
    a1[6]  = ffma2(wF.y, v1.x, a1[6]);   a1[7]  = ffma2(wF.y, v1.y, a1[7]);
}

// Interleaved 32-row dual GEMM, prefetch distance 1, immediate offsets.
__device__ __forceinline__ void gemm_dual(const ulonglong2* __restrict__ v0p,
                                          const ulonglong2* __restrict__ v1p,
                                          const ull* __restrict__ w0,
                                          const ull* __restrict__ w1,
                                          ull* __restrict__ a0, ull* __restrict__ a1) {
    ulonglong2 v0 = v0p[0];
    ulonglong2 v1 = v1p[0];
#pragma unroll 4
    for (int r = 0; r < 31; r++) {
        ulonglong2 nv0 = v0p[(r + 1) * 16];       // row stride = 16 ulonglong2
        ulonglong2 nv1 = v1p[(r + 1) * 16];
        fma_row(w0 + r * 16, w1 + r * 8, v0, v1, a0, a1);
        v0 = nv0; v1 = nv1;
    }
    fma_row(w0 + 31 * 16, w1 + 31 * 8, v0, v1, a0, a1);
}

// Edge-step fallbacks (t=0,1,T): single-layer 32-row slices, depth-2 ring.
__device__ __forceinline__ void gemm32_c8(const ulonglong2* __restrict__ vsrc,
                                          const ull* __restrict__ wp,
                                          ull* __restrict__ a) {
    ulonglong2 v0 = vsrc[0];
#pragma unroll 4
    for (int r = 0; r < 31; r++) {
        ulonglong2 nv = vsrc[(r + 1) * 16];
        const ull* w = wp + r * 16;
        ulonglong2 wA = *reinterpret_cast<const ulonglong2*>(w);
        ulonglong2 wB = *reinterpret_cast<const ulonglong2*>(w + 2);
        ulonglong2 wC = *reinterpret_cast<const ulonglong2*>(w + 4);
        ulonglong2 wD = *reinterpret_cast<const ulonglong2*>(w + 6);
        a[0]  = ffma2(wA.x, v0.x, a[0]);   a[1]  = ffma2(wA.x, v0.y, a[1]);
        a[2]  = ffma2(wA.y, v0.x, a[2]);   a[3]  = ffma2(wA.y, v0.y, a[3]);
        a[4]  = ffma2(wB.x, v0.x, a[4]);   a[5]  = ffma2(wB.x, v0.y, a[5]);
        a[6]  = ffma2(wB.y, v0.x, a[6]);   a[7]  = ffma2(wB.y, v0.y, a[7]);
        a[8]  = ffma2(wC.x, v0.x, a[8]);   a[9]  = ffma2(wC.x, v0.y, a[9]);
        a[10] = ffma2(wC.y, v0.x, a[10]);  a[11] = ffma2(wC.y, v0.y, a[11]);
        a[12] = ffma2(wD.x, v0.x, a[12]);  a[13] = ffma2(wD.x, v0.y, a[13]);
        a[14] = ffma2(wD.y, v0.x, a[14]);  a[15] = ffma2(wD.y, v0.y, a[15]);
        v0 = nv;
    }
    const ull* w = wp + 31 * 16;
    ulonglong2 wA = *reinterpret_cast<const ulonglong2*>(w);
    ulonglong2 wB = *reinterpret_cast<const ulonglong2*>(w + 2);
    ulonglong2 wC = *reinterpret_cast<const ulonglong2*>(w + 4);
    ulonglong2 wD = *reinterpret_cast<const ulonglong2*>(w + 6);
    a[0]  = ffma2(wA.x, v0.x, a[0]);   a[1]  = ffma2(wA.x, v0.y, a[1]);
    a[2]  = ffma2(wA.y, v0.x, a[2]);   a[3]  = ffma2(wA.y, v0.y, a[3]);
    a[4]  = ffma2(wB.x, v0.x, a[4]);   a[5]  = ffma2(wB.x, v0.y, a[5]);
    a[6]  = ffma2(wB.y, v0.x, a[6]);   a[7]  = ffma2(wB.y, v0.y, a[7]);
    a[8]  = ffma2(wC.x, v0.x, a[8]);   a[9]  = ffma2(wC.x, v0.y, a[9]);
    a[10] = ffma2(wC.y, v0.x, a[10]);  a[11] = ffma2(wC.y, v0.y, a[11]);
    a[12] = ffma2(wD.x, v0.x, a[12]);  a[13] = ffma2(wD.x, v0.y, a[13]);
    a[14] = ffma2(wD.y, v0.x, a[14]);  a[15] = ffma2(wD.y, v0.y, a[15]);
}

__device__ __forceinline__ void gemm32_c4(const ulonglong2* __restrict__ vsrc,
                                          const ull* __restrict__ wp,
                                          ull* __restrict__ a) {
    ulonglong2 v0 = vsrc[0];
#pragma unroll 4
    for (int r = 0; r < 31; r++) {
        ulonglong2 nv = vsrc[(r + 1) * 16];
        const ull* w = wp + r * 8;
        ulonglong2 wA = *reinterpret_cast<const ulonglong2*>(w);
        ulonglong2 wB = *reinterpret_cast<const ulonglong2*>(w + 2);
        a[0] = ffma2(wA.x, v0.x, a[0]);  a[1] = ffma2(wA.x, v0.y, a[1]);
        a[2] = ffma2(wA.y, v0.x, a[2]);  a[3] = ffma2(wA.y, v0.y, a[3]);
        a[4] = ffma2(wB.x, v0.x, a[4]);  a[5] = ffma2(wB.x, v0.y, a[5]);
        a[6] = ffma2(wB.y, v0.x, a[6]);  a[7] = ffma2(wB.y, v0.y, a[7]);
        v0 = nv;
    }
    const ull* w = wp + 31 * 8;
    ulonglong2 wA = *reinterpret_cast<const ulonglong2*>(w);
    ulonglong2 wB = *reinterpret_cast<const ulonglong2*>(w + 2);
    a[0] = ffma2(wA.x, v0.x, a[0]);  a[1] = ffma2(wA.x, v0.y, a[1]);
    a[2] = ffma2(wA.y, v0.x, a[2]);  a[3] = ffma2(wA.y, v0.y, a[3]);
    a[4] = ffma2(wB.x, v0.x, a[4]);  a[5] = ffma2(wB.x, v0.y, a[5]);
    a[6] = ffma2(wB.y, v0.x, a[6]);  a[7] = ffma2(wB.y, v0.y, a[7]);
}

__global__ void __launch_bounds__(NTHR, 1)
lstm2_kernel(const float* __restrict__ x,
             const float* __restrict__ Wih0, const float* __restrict__ bih0,
             const float* __restrict__ Whh0, const float* __restrict__ bhh0,
             const float* __restrict__ Wih1, const float* __restrict__ bih1,
             const float* __restrict__ Whh1, const float* __restrict__ bhh1,
             float* __restrict__ out)
{
    extern __shared__ char smraw[];
    ull*   w0d    = reinterpret_cast<ull*>(smraw);            // [768][16] lane-dup
    ull*   w1d    = w0d + 768 * 16;                           // [768][8]
    float* bcol   = reinterpret_cast<float*>(w1d + 768 * 8);  // [24] pad 32
    float* gates0 = bcol + 32;                                // [16][64]
    float* gates1 = gates0 + 16 * BATCH;                      // [8][64]
    ull*   red0   = reinterpret_cast<ull*>(gates1 + 8 * BATCH); // [16][12][32]
    ull*   red1   = red0 + 16 * 12 * 32;                      // [8][12][32]

    const int tid = threadIdx.x;
    const int cta = blockIdx.x;
    const int ks  = tid >> 5;            // warp id 0..23: k in [32ks, 32ks+32)
    const int pg  = (tid & 31) >> 1;     // pair group 0..15
    const int cl  = tid & 1;             // col half

    // ---- one-time: transpose x (B,T,K) -> g_xT (T,K,B) ----
    {
        const size_t total = (size_t)BATCH * T_STEPS * 64;    // float4 groups
        for (size_t idx = (size_t)cta * NTHR + tid; idx < total; idx += (size_t)NCTA * NTHR) {
            int b  = (int)(idx & 63);
            size_t r = idx >> 6;
            int kg = (int)(r & 63);
            int t  = (int)(r >> 6);
            float4 v4 = *reinterpret_cast<const float4*>(
                x + ((size_t)b * T_STEPS + t) * 256 + kg * 4);
            float* dst = g_xT + ((size_t)t * 256 + kg * 4) * BATCH + b;
            dst[0 * BATCH] = v4.x;
            dst[1 * BATCH] = v4.y;
            dst[2 * BATCH] = v4.z;
            dst[3 * BATCH] = v4.w;
        }
    }

    // ---- one-time: stage weights into smem (lane-duplicated for f32x2) ----
    for (int idx = tid; idx < 768 * 16; idx += NTHR) {
        int k = idx >> 4, cc = idx & 15;
        int g = cc >> 2, u = cc & 3;
        int j = g * 512 + cta * 4 + u;
        float w = (k < 256) ? Wih0[(size_t)k * 2048 + j]
                            : Whh0[(size_t)(k - 256) * 2048 + j];
        w0d[idx] = dup32(w);
    }
    for (int idx = tid; idx < 768 * 8; idx += NTHR) {
        int k = idx >> 3, cc = idx & 7;
        int g = cc >> 1, u1 = cc & 1;
        int j = g * 256 + cta * 2 + u1;
        float w = (k < 512) ? Wih1[(size_t)k * 1024 + j]
                            : Whh1[(size_t)(k - 512) * 1024 + j];
        w1d[idx] = dup32(w);
    }
    if (tid < 16) {
        int g = tid >> 2, u = tid & 3;
        int j = g * 512 + cta * 4 + u;
        bcol[tid] = bih0[j] + bhh0[j];
    } else if (tid < 24) {
        int cc = tid - 16, g = cc >> 1, u1 = cc & 1;
        int j = g * 256 + cta * 2 + u1;
        bcol[tid] = bih1[j] + bhh1[j];
    }

    float cst = 0.0f;   // c0 for tid<256 (unit tid>>6, batch tid&63); c1 for [256,384)

    __syncthreads();
    grid_barrier();     // g_xT complete

    // ---- main recurrence: iteration t = layer0 step t + layer1 step t-1 ----
    for (int t = 0; t <= T_STEPS; t++) {
        const bool hasL0 = (t < T_STEPS);
        const bool hasL1 = (t >= 1);

        ull a0[16], a1[8];
#pragma unroll
        for (int j = 0; j < 16; j++) a0[j] = 0ull;
#pragma unroll
        for (int j = 0; j < 8; j++) a1[j] = 0ull;

        const bool d0 = hasL0 && (ks < 8 || t >= 1);
        const bool d1 = hasL1 && (ks < 16 || t >= 2);

        const float* s0 = (ks < 8)
            ? (g_xT + (size_t)t * 16384 + ks * 2048)
            : (g_h0[(t - 1) & 1] + (ks - 8) * 2048);
        const float* s1 = (ks < 16)
            ? (g_h0[(t - 1) & 1] + ks * 2048)
            : (g_h1[t & 1] + (ks - 16) * 2048);
        const ulonglong2* v0p = reinterpret_cast<const ulonglong2*>(s0) + pg;
        const ulonglong2* v1p = reinterpret_cast<const ulonglong2*>(s1) + pg;
        const ull* w0 = w0d + (size_t)(32 * ks) * 16 + cl * 8;
        const ull* w1 = w1d + (size_t)(32 * ks) * 8 + cl * 4;

        if (d0 && d1)      gemm_dual(v0p, v1p, w0, w1, a0, a1);
        else if (d0)       gemm32_c8(v0p, w0, a0);
        else if (d1)       gemm32_c4(v1p, w1, a1);

        // ---- 2-wave ks reduction into 12 slots ----
        const int slot = (ks < 12) ? ks : (ks - 12);
        if (ks < 12) {
#pragma unroll
            for (int j = 0; j < 8; j++)
                *reinterpret_cast<ulonglong2*>(
                    red0 + ((cl * 8 + j) * 12 + slot) * 32 + 2 * pg) =
                    make_ulonglong2(a0[2 * j], a0[2 * j + 1]);
#pragma unroll
            for (int j = 0; j < 4; j++)
                *reinterpret_cast<ulonglong2*>(
                    red1 + ((cl * 4 + j) * 12 + slot) * 32 + 2 * pg) =
                    make_ulonglong2(a1[2 * j], a1[2 * j + 1]);
        }
        __syncthreads();
        if (ks >= 12) {
#pragma unroll
            for (int j = 0; j < 8; j++) {
                ull* d = red0 + ((cl * 8 + j) * 12 + slot) * 32 + 2 * pg;
                ulonglong2 r = *reinterpret_cast<ulonglong2*>(d);
                r.x = addf2(r.x, a0[2 * j]); r.y = addf2(r.y, a0[2 * j + 1]);
                *reinterpret_cast<ulonglong2*>(d) = r;
            }
#pragma unroll
            for (int j = 0; j < 4; j++) {
                ull* d = red1 + ((cl * 4 + j) * 12 + slot) * 32 + 2 * pg;
                ulonglong2 r = *reinterpret_cast<ulonglong2*>(d);
                r.x = addf2(r.x, a1[2 * j]); r.y = addf2(r.y, a1[2 * j + 1]);
                *reinterpret_cast<ulonglong2*>(d) = r;
            }
        }
        __syncthreads();

        // ---- final: sum 12 slots + bias -> gates (one ull per thread) ----
        if (tid < 512) {
            int cc = tid >> 5, pr = tid & 31;
            const ull* r = red0 + (cc * 12) * 32 + pr;
            ull s = dup32(bcol[cc]);
#pragma unroll
            for (int w = 0; w < 12; w++) s = addf2(s, r[w * 32]);
            *reinterpret_cast<ull*>(&gates0[cc * 64 + 2 * pr]) = s;
        } else {
            int i = tid - 512, cc = i >> 5, pr = i & 31;
            const ull* r = red1 + (cc * 12) * 32 + pr;
            ull s = dup32(bcol[16 + cc]);
#pragma unroll
            for (int w = 0; w < 12; w++) s = addf2(s, r[w * 32]);
            *reinterpret_cast<ull*>(&gates1[cc * 64 + 2 * pr]) = s;
        }
        __syncthreads();

        // ---- activations (disjoint warps) ----
        if (hasL0 && tid < 256) {
            int u = tid >> 6, b = tid & 63;
            float gi = gates0[(0 * 4 + u) * 64 + b];
            float gf = gates0[(1 * 4 + u) * 64 + b];
            float gg = gates0[(2 * 4 + u) * 64 + b];
            float go = gates0[(3 * 4 + u) * 64 + b];
            cst = sigmf(gf) * cst + sigmf(gi) * tanhf(gg);
            g_h0[t & 1][(cta * 4 + u) * 64 + b] = sigmf(go) * tanhf(cst);
        }
        if (hasL1 && tid >= 256 && tid < 384) {
            int u1 = (tid >> 6) & 1, b = tid & 63;
            float gi = gates1[(0 * 2 + u1) * 64 + b];
            float gf = gates1[(1 * 2 + u1) * 64 + b];
            float gg = gates1[(2 * 2 + u1) * 64 + b];
            float go = gates1[(3 * 2 + u1) * 64 + b];
            cst = sigmf(gf) * cst + sigmf(gi) * tanhf(gg);
            float h = sigmf(go) * tanhf(cst);
            int s = t - 1;
            g_h1[s & 1][(cta * 2 + u1) * 64 + b] = h;
            out[((size_t)b * T_STEPS + s) * 256 + cta * 2 + u1] = h;
        }

        if (t < T_STEPS) grid_barrier();
    }
}

// smem: w0d 98304 + w1d 49152 + bcol 128 + gates 6144 + red0 49152 + red1 24576 = 227456
#define SMEM_BYTES (98304 + 49152 + 128 + 4096 + 2048 + 49152 + 24576)

extern "C" void kernel_launch(void* const* d_in, const int* in_sizes, int n_in,
                              void* d_out, int out_size) {
    (void)in_sizes; (void)n_in; (void)out_size;
    cudaFuncSetAttribute(lstm2_kernel,
                         cudaFuncAttributeMaxDynamicSharedMemorySize, SMEM_BYTES);
    lstm2_kernel<<<NCTA, NTHR, SMEM_BYTES>>>(
        (const float*)d_in[0],
        (const float*)d_in[1], (const float*)d_in[2],
        (const float*)d_in[3], (const float*)d_in[4],
        (const float*)d_in[5], (const float*)d_in[6],
        (const float*)d_in[7], (const float*)d_in[8],
        (float*)d_out);
}